// round 1
// baseline (speedup 1.0000x reference)
#include <cuda_runtime.h>
#include <math.h>

#define BB 64
#define CC 32
#define LL 6400
#define NH 8
#define INV_PI 0.318309886183790671538f

typedef unsigned long long ull;

// ---------------- f32x2 packed-math helpers ----------------
__device__ __forceinline__ ull pack2(float lo, float hi){
    ull r; asm("mov.b64 %0,{%1,%2};" : "=l"(r) : "f"(lo), "f"(hi)); return r;
}
__device__ __forceinline__ void fma2(ull& d, ull a, ull b){
    asm("fma.rn.f32x2 %0,%1,%2,%0;" : "+l"(d) : "l"(a), "l"(b));
}
__device__ __forceinline__ float hsum2(ull v){
    float lo, hi; asm("mov.b64 {%0,%1},%2;" : "=f"(lo), "=f"(hi) : "l"(v)); return lo + hi;
}
// 32-term dot product: wrow = 16 packed pairs (shared), xp = 16 packed pairs (regs)
__device__ __forceinline__ float dot16(const ull* wrow, const ull* xp){
    ull a0 = 0ULL, a1 = 0ULL;
    #pragma unroll
    for(int cc=0; cc<16; cc+=2){ fma2(a0, wrow[cc], xp[cc]); fma2(a1, wrow[cc+1], xp[cc+1]); }
    return hsum2(a0) + hsum2(a1);
}

// ---------------- scratch (no allocations allowed) ----------------
__device__ float g_q1[BB*CC*LL];
__device__ float g_k1[BB*CC*LL];
__device__ float g_v1[BB*CC*LL];
__device__ float g_q2[BB*CC*LL];
__device__ float g_k2[BB*CC*LL];
__device__ float g_v2[BB*CC*LL];
__device__ float g_f1[BB*CC*LL];
__device__ float g_f2[BB*CC*LL];
__device__ float g_attn1[BB*NH*16];
__device__ float g_attn2[BB*NH*16];
__device__ float g_avg[2*BB*CC];
__device__ float g_mx[2*BB*CC];
__device__ float g_w1[BB*CC*CC];
__device__ float g_w2[BB*CC*CC];
__device__ float g_pool[4*BB*LL];   // [s*2+ch][b][l] ch: 0=mean,1=max
__device__ float g_gate[BB*2*LL];   // [b][s][l]

// ---------------- K1/K4: qkv GEMM (+ per-head q,k norm for lin path) ----------------
// S=0: lin-angular (normalize q,k over HD). S=1: XCA (raw).
template<int S>
__global__ __launch_bounds__(128) void qkv_kernel(const float* __restrict__ x,
                                                  const float* __restrict__ w){
    __shared__ ull sw[96*16];
    int tid = threadIdx.x;
    const ull* wg = (const ull*)w;
    for(int i=tid; i<1536; i+=128) sw[i] = wg[i];
    __syncthreads();
    int b = blockIdx.y;
    int l = blockIdx.x*128 + tid;
    const float* xb = x + b*CC*LL + l;
    ull xp[16];
    #pragma unroll
    for(int c=0;c<16;c++) xp[c] = pack2(xb[(2*c)*LL], xb[(2*c+1)*LL]);
    float* qb = (S ? g_q2 : g_q1) + b*CC*LL + l;
    float* kb = (S ? g_k2 : g_k1) + b*CC*LL + l;
    float* vb = (S ? g_v2 : g_v1) + b*CC*LL + l;
    #pragma unroll
    for(int h=0;h<NH;h++){
        float qv[4], kv[4], vv[4];
        #pragma unroll
        for(int d=0;d<4;d++){
            int j = h*4+d;
            qv[d] = dot16(sw + j*16,      xp);
            kv[d] = dot16(sw + (32+j)*16, xp);
            vv[d] = dot16(sw + (64+j)*16, xp);
        }
        if(S==0){
            float sq = qv[0]*qv[0]+qv[1]*qv[1]+qv[2]*qv[2]+qv[3]*qv[3];
            float sk = kv[0]*kv[0]+kv[1]*kv[1]+kv[2]*kv[2]+kv[3]*kv[3];
            float iq = rsqrtf(sq), ik = rsqrtf(sk);
            #pragma unroll
            for(int d=0;d<4;d++){ qv[d]*=iq; kv[d]*=ik; }
        }
        #pragma unroll
        for(int d=0;d<4;d++){
            qb[(h*4+d)*LL] = qv[d];
            kb[(h*4+d)*LL] = kv[d];
            vb[(h*4+d)*LL] = vv[d];
        }
    }
}

// ---------------- K2: lin-angular attn = INV_PI * sum_l outer(kn, v) per (b,h) ----------------
__global__ __launch_bounds__(256) void attn_lin_kernel(){
    int bh = blockIdx.x; int b = bh>>3, h = bh&7;
    const float* kb = g_k1 + (b*CC + h*4)*LL;
    const float* vb = g_v1 + (b*CC + h*4)*LL;
    float p[16];
    #pragma unroll
    for(int i=0;i<16;i++) p[i]=0.f;
    for(int l=threadIdx.x; l<LL; l+=256){
        float kk[4], vv[4];
        #pragma unroll
        for(int d=0;d<4;d++){ kk[d]=kb[d*LL+l]; vv[d]=vb[d*LL+l]; }
        #pragma unroll
        for(int d=0;d<4;d++)
            #pragma unroll
            for(int e=0;e<4;e++) p[d*4+e] += kk[d]*vv[e];
    }
    __shared__ float sp[8][16];
    int lane = threadIdx.x&31, wid = threadIdx.x>>5;
    #pragma unroll
    for(int i=0;i<16;i++){
        float v = p[i];
        #pragma unroll
        for(int o=16;o>0;o>>=1) v += __shfl_xor_sync(0xffffffffu, v, o);
        if(lane==0) sp[wid][i]=v;
    }
    __syncthreads();
    if(threadIdx.x<16){
        float s=0.f;
        #pragma unroll
        for(int wq=0;wq<8;wq++) s += sp[wq][threadIdx.x];
        g_attn1[bh*16+threadIdx.x] = INV_PI * s;
    }
}

// ---------------- K5: XCA gram + L-norms + temp-scaled row softmax per (b,h) ----------------
__global__ __launch_bounds__(256) void attn_xca_kernel(const float* __restrict__ temp){
    int bh = blockIdx.x; int b = bh>>3, h = bh&7;
    const float* qb = g_q2 + (b*CC + h*4)*LL;
    const float* kb = g_k2 + (b*CC + h*4)*LL;
    float part[24];
    #pragma unroll
    for(int i=0;i<24;i++) part[i]=0.f;
    for(int l=threadIdx.x; l<LL; l+=256){
        float qq[4], kk[4];
        #pragma unroll
        for(int d=0;d<4;d++){ qq[d]=qb[d*LL+l]; kk[d]=kb[d*LL+l]; }
        #pragma unroll
        for(int d=0;d<4;d++){
            part[16+d] += qq[d]*qq[d];
            part[20+d] += kk[d]*kk[d];
            #pragma unroll
            for(int e=0;e<4;e++) part[d*4+e] += qq[d]*kk[e];
        }
    }
    __shared__ float sp[8][24];
    __shared__ float red[24];
    int lane = threadIdx.x&31, wid = threadIdx.x>>5;
    #pragma unroll
    for(int i=0;i<24;i++){
        float v = part[i];
        #pragma unroll
        for(int o=16;o>0;o>>=1) v += __shfl_xor_sync(0xffffffffu, v, o);
        if(lane==0) sp[wid][i]=v;
    }
    __syncthreads();
    if(threadIdx.x<24){
        float s=0.f;
        #pragma unroll
        for(int wq=0;wq<8;wq++) s += sp[wq][threadIdx.x];
        red[threadIdx.x]=s;
    }
    __syncthreads();
    if(threadIdx.x<4){
        int d = threadIdx.x;
        float qn = fmaxf(sqrtf(red[16+d]), 1e-12f);
        float tt = temp[h];
        float vals[4]; float m = -3.4e38f;
        #pragma unroll
        for(int e=0;e<4;e++){
            float kn = fmaxf(sqrtf(red[20+e]), 1e-12f);
            vals[e] = red[d*4+e] / (qn*kn) * tt;
            m = fmaxf(m, vals[e]);
        }
        float s=0.f;
        #pragma unroll
        for(int e=0;e<4;e++){ vals[e]=expf(vals[e]-m); s+=vals[e]; }
        float inv = 1.f/s;
        #pragma unroll
        for(int e=0;e<4;e++) g_attn2[bh*16 + d*4 + e] = vals[e]*inv;
    }
}

// ---------------- K3: lin finish: 0.5v + q@attn, norm, +dconv, proj -> f1 ----------------
__global__ __launch_bounds__(128) void lin_out_kernel(const float* __restrict__ dconv_w,
                                                      const float* __restrict__ projw,
                                                      const float* __restrict__ projb){
    __shared__ float attnS[128];
    __shared__ float w9[72];
    __shared__ ull pw[512];
    __shared__ float pb[32];
    int tid = threadIdx.x, b = blockIdx.y;
    attnS[tid] = g_attn1[b*128 + tid];
    if(tid<72) w9[tid] = dconv_w[tid];
    if(tid<32) pb[tid] = projb[tid];
    const ull* pwg = (const ull*)projw;
    for(int i=tid;i<512;i+=128) pw[i]=pwg[i];
    __syncthreads();
    int l = blockIdx.x*128 + tid;
    const float* qb = g_q1 + b*CC*LL + l;
    const float* vb = g_v1 + b*CC*LL + l;
    float o[32];
    #pragma unroll
    for(int h=0;h<8;h++){
        float qv[4], vv[4];
        #pragma unroll
        for(int d=0;d<4;d++){ qv[d]=qb[(h*4+d)*LL]; vv[d]=vb[(h*4+d)*LL]; }
        float ov[4]; float s = 0.f;
        #pragma unroll
        for(int e=0;e<4;e++){
            float t = 0.5f*vv[e];
            #pragma unroll
            for(int d=0;d<4;d++) t += qv[d]*attnS[h*16 + d*4 + e];
            ov[e]=t; s += t*t;
        }
        float inv = rsqrtf(s);
        #pragma unroll
        for(int d=0;d<4;d++){
            float acc = 0.f;
            #pragma unroll
            for(int t9=0;t9<9;t9++){
                int ll = l + t9 - 4;
                if(ll>=0 && ll<LL) acc += w9[h*9+t9]*vb[(h*4+d)*LL + (t9-4)];
            }
            o[h*4+d] = ov[d]*inv + acc;
        }
    }
    ull op[16];
    #pragma unroll
    for(int cc=0;cc<16;cc++) op[cc]=pack2(o[2*cc], o[2*cc+1]);
    float* fb = g_f1 + b*CC*LL + l;
    #pragma unroll
    for(int c=0;c<32;c++){
        ull a0=0ULL, a1=0ULL;
        #pragma unroll
        for(int cc=0;cc<16;cc+=2){ fma2(a0,pw[c*16+cc],op[cc]); fma2(a1,pw[c*16+cc+1],op[cc+1]); }
        fb[c*LL] = hsum2(a0)+hsum2(a1)+pb[c];
    }
}

// ---------------- K6: XCA finish: attn@v, proj -> f2 ----------------
__global__ __launch_bounds__(128) void xca_out_kernel(const float* __restrict__ projw,
                                                      const float* __restrict__ projb){
    __shared__ float attnS[128];
    __shared__ ull pw[512];
    __shared__ float pb[32];
    int tid = threadIdx.x, b = blockIdx.y;
    attnS[tid] = g_attn2[b*128 + tid];
    if(tid<32) pb[tid] = projb[tid];
    const ull* pwg = (const ull*)projw;
    for(int i=tid;i<512;i+=128) pw[i]=pwg[i];
    __syncthreads();
    int l = blockIdx.x*128 + tid;
    const float* vb = g_v2 + b*CC*LL + l;
    float o[32];
    #pragma unroll
    for(int h=0;h<8;h++){
        float vv[4];
        #pragma unroll
        for(int e=0;e<4;e++) vv[e]=vb[(h*4+e)*LL];
        #pragma unroll
        for(int d=0;d<4;d++){
            float t = 0.f;
            #pragma unroll
            for(int e=0;e<4;e++) t += attnS[h*16 + d*4 + e]*vv[e];
            o[h*4+d]=t;
        }
    }
    ull op[16];
    #pragma unroll
    for(int cc=0;cc<16;cc++) op[cc]=pack2(o[2*cc], o[2*cc+1]);
    float* fb = g_f2 + b*CC*LL + l;
    #pragma unroll
    for(int c=0;c<32;c++){
        ull a0=0ULL, a1=0ULL;
        #pragma unroll
        for(int cc=0;cc<16;cc+=2){ fma2(a0,pw[c*16+cc],op[cc]); fma2(a1,pw[c*16+cc+1],op[cc+1]); }
        fb[c*LL] = hsum2(a0)+hsum2(a1)+pb[c];
    }
}

// ---------------- K7: per-(stream,b,c) avg/max pooling over L ----------------
__global__ __launch_bounds__(256) void pool_kernel(){
    int id = blockIdx.x; // s*2048 + b*32 + c
    const float* f = (id >= BB*CC) ? (g_f2 + (id-BB*CC)*LL) : (g_f1 + id*LL);
    float sm = 0.f, mx = -3.4e38f;
    for(int l=threadIdx.x; l<LL; l+=256){ float v=f[l]; sm+=v; mx=fmaxf(mx,v); }
    __shared__ float s1[8], s2[8];
    int lane = threadIdx.x&31, wid = threadIdx.x>>5;
    #pragma unroll
    for(int o=16;o>0;o>>=1){ sm += __shfl_xor_sync(0xffffffffu,sm,o); mx = fmaxf(mx,__shfl_xor_sync(0xffffffffu,mx,o)); }
    if(lane==0){ s1[wid]=sm; s2[wid]=mx; }
    __syncthreads();
    if(threadIdx.x==0){
        float a=0.f, m=-3.4e38f;
        #pragma unroll
        for(int w=0;w<8;w++){ a+=s1[w]; m=fmaxf(m,s2[w]); }
        g_avg[id]=a; g_mx[id]=m;
    }
}

// ---------------- K8: CAFM channel MLPs + cross softmax weight matrices ----------------
__global__ __launch_bounds__(64) void cafm_kernel(
    const float* __restrict__ aw1,  const float* __restrict__ ab1,
    const float* __restrict__ mw1,  const float* __restrict__ mb1,
    const float* __restrict__ aw2,  const float* __restrict__ ab2,
    const float* __restrict__ mw2,  const float* __restrict__ mb2,
    const float* __restrict__ aw11, const float* __restrict__ ab11,
    const float* __restrict__ mw11, const float* __restrict__ mb11,
    const float* __restrict__ aw22, const float* __restrict__ ab22,
    const float* __restrict__ mw22, const float* __restrict__ mb22){
    int b = blockIdx.x, t = threadIdx.x;
    __shared__ float sa[4][32], hid[4][16], a1s[32], a2s[32];
    if(t<32){
        sa[0][t] = g_avg[b*32+t] * (1.0f/LL);
        sa[1][t] = g_mx[b*32+t];
        sa[2][t] = g_avg[BB*CC + b*32+t] * (1.0f/LL);
        sa[3][t] = g_mx[BB*CC + b*32+t];
    }
    __syncthreads();
    {
        int br = t>>4, hh = t&15;
        const float* w  = (br==0)?aw1 : (br==1)?mw1 : (br==2)?aw2 : mw2;
        const float* bi = (br==0)?ab1 : (br==1)?mb1 : (br==2)?ab2 : mb2;
        float s = bi[hh];
        #pragma unroll
        for(int c=0;c<32;c++) s += sa[br][c]*w[hh*32+c];
        hid[br][hh] = fmaxf(s, 0.f);
    }
    __syncthreads();
    if(t<32){
        float s = ab11[t] + mb11[t];
        #pragma unroll
        for(int h=0;h<16;h++) s += hid[0][h]*aw11[t*16+h] + hid[1][h]*mw11[t*16+h];
        a1s[t]=s;
    } else {
        int c = t-32;
        float s = ab22[c] + mb22[c];
        #pragma unroll
        for(int h=0;h<16;h++) s += hid[2][h]*aw22[c*16+h] + hid[3][h]*mw22[c*16+h];
        a2s[c]=s;
    }
    __syncthreads();
    if(t<32){
        float a = a1s[t];
        float e[32]; float m = -3.4e38f;
        #pragma unroll
        for(int d=0;d<32;d++){ e[d]=a*a2s[d]; m=fmaxf(m,e[d]); }
        float s=0.f;
        #pragma unroll
        for(int d=0;d<32;d++){ e[d]=expf(e[d]-m); s+=e[d]; }
        float inv = 1.f/s;
        #pragma unroll
        for(int d=0;d<32;d++) g_w1[b*1024 + t*32 + d] = e[d]*inv;
    } else {
        int c = t-32;
        float a = a2s[c];
        float e[32]; float m = -3.4e38f;
        #pragma unroll
        for(int d=0;d<32;d++){ e[d]=a*a1s[d]; m=fmaxf(m,e[d]); }
        float s=0.f;
        #pragma unroll
        for(int d=0;d<32;d++){ e[d]=expf(e[d]-m); s+=e[d]; }
        float inv = 1.f/s;
        #pragma unroll
        for(int d=0;d<32;d++) g_w2[b*1024 + c*32 + d] = e[d]*inv;
    }
}

// ---------------- K9: a1f/a2f matvec + channel mean/max pooling -> g_pool ----------------
__global__ __launch_bounds__(128) void a1f_pool_kernel(){
    __shared__ ull w1s[512], w2s[512];
    int tid = threadIdx.x, b = blockIdx.y;
    const ull* w1g = (const ull*)(g_w1 + b*1024);
    const ull* w2g = (const ull*)(g_w2 + b*1024);
    for(int i=tid;i<512;i+=128){ w1s[i]=w1g[i]; w2s[i]=w2g[i]; }
    __syncthreads();
    int l = blockIdx.x*128 + tid;
    const float* f1b = g_f1 + b*CC*LL + l;
    const float* f2b = g_f2 + b*CC*LL + l;
    ull f1p[16], f2p[16];
    #pragma unroll
    for(int cc=0;cc<16;cc++){
        f1p[cc] = pack2(f1b[(2*cc)*LL], f1b[(2*cc+1)*LL]);
        f2p[cc] = pack2(f2b[(2*cc)*LL], f2b[(2*cc+1)*LL]);
    }
    float s1=0.f, m1=-3.4e38f, s2=0.f, m2=-3.4e38f;
    #pragma unroll
    for(int c=0;c<32;c++){
        ull a0=0ULL,a1=0ULL,b0=0ULL,b1=0ULL;
        #pragma unroll
        for(int cc=0;cc<16;cc+=2){
            fma2(a0,w1s[c*16+cc],f1p[cc]);   fma2(a1,w1s[c*16+cc+1],f1p[cc+1]);
            fma2(b0,w2s[c*16+cc],f2p[cc]);   fma2(b1,w2s[c*16+cc+1],f2p[cc+1]);
        }
        float v1 = hsum2(a0)+hsum2(a1);
        float v2 = hsum2(b0)+hsum2(b1);
        s1+=v1; m1=fmaxf(m1,v1);
        s2+=v2; m2=fmaxf(m2,v2);
    }
    g_pool[(0*BB+b)*LL + l] = s1*(1.f/32.f);
    g_pool[(1*BB+b)*LL + l] = m1;
    g_pool[(2*BB+b)*LL + l] = s2*(1.f/32.f);
    g_pool[(3*BB+b)*LL + l] = m2;
}

// ---------------- K10: spatial gate: conv3x3(2->1)+relu, conv3x3(1->1), softmax over L ----------------
__global__ __launch_bounds__(256) void gate_kernel(const float* __restrict__ c1w,
                                                   const float* __restrict__ c1b,
                                                   const float* __restrict__ c2w,
                                                   const float* __restrict__ c2b){
    __shared__ float y1[LL];
    __shared__ float red[8];
    int t = threadIdx.x;
    int b = blockIdx.x>>1, s = blockIdx.x&1;
    const float* pm = g_pool + ((s*2+0)*BB + b)*LL;
    const float* px = g_pool + ((s*2+1)*BB + b)*LL;
    float w1c[18];
    #pragma unroll
    for(int i=0;i<18;i++) w1c[i]=c1w[i];
    float b1 = c1b[0];
    for(int l=t; l<LL; l+=256){
        int iy = l/80, ix = l%80;
        float acc = b1;
        #pragma unroll
        for(int ky=0;ky<3;ky++){
            int yy = iy+ky-1; if(yy<0||yy>=80) continue;
            #pragma unroll
            for(int kx=0;kx<3;kx++){
                int xx = ix+kx-1; if(xx<0||xx>=80) continue;
                int p = yy*80+xx;
                acc += w1c[ky*3+kx]*pm[p] + w1c[9+ky*3+kx]*px[p];
            }
        }
        y1[l] = fmaxf(acc, 0.f);
    }
    __syncthreads();
    float w2c[9];
    #pragma unroll
    for(int i=0;i<9;i++) w2c[i]=c2w[i];
    float b2 = c2b[0];
    float r[25]; float mx = -3.4e38f;
    #pragma unroll
    for(int i=0;i<25;i++){
        int l = t + i*256;
        int iy = l/80, ix = l%80;
        float acc = b2;
        #pragma unroll
        for(int ky=0;ky<3;ky++){
            int yy = iy+ky-1; if(yy<0||yy>=80) continue;
            #pragma unroll
            for(int kx=0;kx<3;kx++){
                int xx = ix+kx-1; if(xx<0||xx>=80) continue;
                acc += w2c[ky*3+kx]*y1[yy*80+xx];
            }
        }
        r[i]=acc; mx=fmaxf(mx,acc);
    }
    int lane = t&31, wid = t>>5;
    #pragma unroll
    for(int o=16;o>0;o>>=1) mx = fmaxf(mx, __shfl_xor_sync(0xffffffffu,mx,o));
    if(lane==0) red[wid]=mx;
    __syncthreads();
    if(t==0){ float m=red[0]; for(int w=1;w<8;w++) m=fmaxf(m,red[w]); red[0]=m; }
    __syncthreads();
    float m = red[0];
    __syncthreads();
    float sm = 0.f;
    #pragma unroll
    for(int i=0;i<25;i++){ r[i]=expf(r[i]-m); sm+=r[i]; }
    #pragma unroll
    for(int o=16;o>0;o>>=1) sm += __shfl_xor_sync(0xffffffffu,sm,o);
    if(lane==0) red[wid]=sm;
    __syncthreads();
    if(t==0){ float a=0.f; for(int w=0;w<8;w++) a+=red[w]; red[0]=a; }
    __syncthreads();
    float inv = 1.f/red[0];
    #pragma unroll
    for(int i=0;i<25;i++) g_gate[(b*2+s)*LL + t + i*256] = r[i]*inv;
}

// ---------------- K11: out = f1*(1+g1) + f2*(1+g2) ----------------
__global__ __launch_bounds__(256) void final_kernel(float* __restrict__ out){
    int i = blockIdx.x*256 + threadIdx.x;       // one float4 per thread
    int idx = i*4;
    int b = idx/(CC*LL);
    int l = idx%LL;
    float4 a  = ((const float4*)g_f1)[i];
    float4 c  = ((const float4*)g_f2)[i];
    float4 g1 = *(const float4*)&g_gate[(b*2+0)*LL + l];
    float4 g2 = *(const float4*)&g_gate[(b*2+1)*LL + l];
    float4 o;
    o.x = a.x*(1.f+g1.x) + c.x*(1.f+g2.x);
    o.y = a.y*(1.f+g1.y) + c.y*(1.f+g2.y);
    o.z = a.z*(1.f+g1.z) + c.z*(1.f+g2.z);
    o.w = a.w*(1.f+g1.w) + c.w*(1.f+g2.w);
    ((float4*)out)[i] = o;
}

// ---------------- launch ----------------
extern "C" void kernel_launch(void* const* d_in, const int* in_sizes, int n_in,
                              void* d_out, int out_size){
    const float* rgb       = (const float*)d_in[0];
    const float* freq      = (const float*)d_in[1];
    const float* la_qkv_w  = (const float*)d_in[2];
    const float* la_proj_w = (const float*)d_in[3];
    const float* la_proj_b = (const float*)d_in[4];
    const float* la_dconv_w= (const float*)d_in[5];
    const float* xa_qkv_w  = (const float*)d_in[6];
    const float* xa_temp   = (const float*)d_in[7];
    const float* xa_proj_w = (const float*)d_in[8];
    const float* xa_proj_b = (const float*)d_in[9];
    const float* c1s_w     = (const float*)d_in[10];
    const float* c1s_b     = (const float*)d_in[11];
    const float* c2s_w     = (const float*)d_in[12];
    const float* c2s_b     = (const float*)d_in[13];

    dim3 gpix(LL/128, BB);
    qkv_kernel<0><<<gpix,128>>>(rgb,  la_qkv_w);
    qkv_kernel<1><<<gpix,128>>>(freq, xa_qkv_w);
    attn_lin_kernel<<<BB*NH,256>>>();
    attn_xca_kernel<<<BB*NH,256>>>(xa_temp);
    lin_out_kernel<<<gpix,128>>>(la_dconv_w, la_proj_w, la_proj_b);
    xca_out_kernel<<<gpix,128>>>(xa_proj_w, xa_proj_b);
    pool_kernel<<<2*BB*CC,256>>>();
    cafm_kernel<<<BB,64>>>((const float*)d_in[14],(const float*)d_in[15],
                           (const float*)d_in[16],(const float*)d_in[17],
                           (const float*)d_in[18],(const float*)d_in[19],
                           (const float*)d_in[20],(const float*)d_in[21],
                           (const float*)d_in[22],(const float*)d_in[23],
                           (const float*)d_in[24],(const float*)d_in[25],
                           (const float*)d_in[26],(const float*)d_in[27],
                           (const float*)d_in[28],(const float*)d_in[29]);
    a1f_pool_kernel<<<gpix,128>>>();
    gate_kernel<<<BB*2,256>>>(c1s_w, c1s_b, c2s_w, c2s_b);
    final_kernel<<<(BB*CC*LL/4)/256,256>>>((float*)d_out);
}